// round 3
// baseline (speedup 1.0000x reference)
#include <cuda_runtime.h>
#include <cstddef>

// ---------------- scratch (no allocations allowed -> __device__ globals) ----
#define MAX_EDGES 2000000
#define MAX_NODES 100000

__device__ float g_bufA[(size_t)MAX_EDGES * 160];
__device__ float g_bufB[(size_t)MAX_EDGES * 160];
__device__ float g_eprime[(size_t)MAX_NODES * 64];

// ---------------- gather: build R_prime [M,16] ----------------------------
__global__ void gather_kernel(const float* __restrict__ x,
                              const float* __restrict__ ofx,
                              const int* __restrict__ src,
                              const int* __restrict__ tgt,
                              const float* __restrict__ t,
                              float* __restrict__ out, int M)
{
    int e = blockIdx.x * blockDim.x + threadIdx.x;
    if (e >= M) return;
    int s = src[e], g = tgt[e];
    float4 xs = *(const float4*)(x + (size_t)4 * s);
    float2 os = *(const float2*)(ofx + (size_t)2 * s);
    float4 xt = *(const float4*)(x + (size_t)4 * g);
    float2 ot = *(const float2*)(ofx + (size_t)2 * g);
    float tv = t[0];
    float4* o = (float4*)(out + (size_t)e * 16);
    o[0] = xs;
    o[1] = make_float4(os.x, os.y, xt.x, xt.y);
    o[2] = make_float4(xt.z, xt.w, ot.x, ot.y);
    o[3] = make_float4(tv, 0.f, 0.f, 0.f);
}

// ---------------- zero E' --------------------------------------------------
__global__ void zero_kernel(float* __restrict__ p, int n)
{
    int i = blockIdx.x * blockDim.x + threadIdx.x;
    if (i < n) p[i] = 0.f;
}

// ---------------- scatter-add: E[M,50] (stride 64) -> E'[N,64] -------------
__global__ void scatter_kernel(const float* __restrict__ E,
                               const int* __restrict__ tgt,
                               float* __restrict__ ep, int M)
{
    int idx = blockIdx.x * blockDim.x + threadIdx.x;
    int e = idx >> 5;
    if (e >= M) return;
    int lane = idx & 31;
    int tg = __ldg(tgt + e);
    const float* Er = E + (size_t)e * 64;
    float* dst = ep + (size_t)tg * 64;
    atomicAdd(dst + lane, Er[lane]);
    if (lane < 18) atomicAdd(dst + lane + 32, Er[lane + 32]);
}

// ---------------- fp32 GEMM + bias + optional ReLU -------------------------
// C[M,dout-ish] = act(A[M,din] * W[din,dout] + b)
// Weights fully resident in smem (zero-padded to [din4][PN]). NO smem A tile,
// NO barriers in the main loop: each warp owns independent 8-row strips and
// streams A rows from gmem with LDG.128. 256 thr, 2 CTAs/SM -> 4 warps/SMSP.
template <int NS>
__global__ __launch_bounds__(256, 2)
void gemm_kernel(const float* __restrict__ A, int lda,
                 const float* __restrict__ W, const float* __restrict__ B,
                 float* __restrict__ C, int ldc,
                 int M, int din, int dout, int relu, int padstore)
{
    constexpr int PN = NS * 32;
    extern __shared__ float smem[];
    float* Ws = smem;                 // [din4][PN], zero-padded
    float* Bs = Ws + ((din + 3) & ~3) * PN;   // [PN]
    const int tid = threadIdx.x;
    const int din4 = (din + 3) & ~3;

    for (int idx = tid; idx < din4 * PN; idx += 256) {
        int k = idx / PN;
        int j = idx - k * PN;
        Ws[idx] = (k < din && j < dout) ? W[(size_t)k * dout + j] : 0.f;
    }
    for (int j = tid; j < PN; j += 256)
        Bs[j] = (j < dout) ? B[j] : 0.f;
    __syncthreads();

    const int lane = tid & 31;
    const int gwarp = blockIdx.x * 8 + (tid >> 5);
    const int nwarp = gridDim.x * 8;
    const int nstrips = (M + 7) >> 3;

    for (int sidx = gwarp; sidx < nstrips; sidx += nwarp) {
        const int row0 = sidx << 3;

        const float* ap[8];
#pragma unroll
        for (int r = 0; r < 8; r++) {
            int rr = row0 + r;
            if (rr > M - 1) rr = M - 1;     // clamp (results discarded)
            ap[r] = A + (size_t)rr * lda;
        }

        float acc[8][NS];
#pragma unroll
        for (int r = 0; r < 8; r++)
#pragma unroll
            for (int s = 0; s < NS; s++) acc[r][s] = 0.f;

#pragma unroll 2
        for (int k = 0; k < din4; k += 4) {
            float4 a[8];
#pragma unroll
            for (int r = 0; r < 8; r++)
                a[r] = *(const float4*)(ap[r] + k);

#pragma unroll
            for (int kk = 0; kk < 4; kk++) {
                float wv[NS];
#pragma unroll
                for (int s = 0; s < NS; s++)
                    wv[s] = Ws[(k + kk) * PN + lane + (s << 5)];
#pragma unroll
                for (int r = 0; r < 8; r++) {
                    float av = (kk == 0) ? a[r].x : (kk == 1) ? a[r].y
                             : (kk == 2) ? a[r].z : a[r].w;
#pragma unroll
                    for (int s = 0; s < NS; s++)
                        acc[r][s] = fmaf(av, wv[s], acc[r][s]);
                }
            }
        }

#pragma unroll
        for (int r = 0; r < 8; r++) {
            int row = row0 + r;
            if (row < M) {
#pragma unroll
                for (int s = 0; s < NS; s++) {
                    int j = lane + (s << 5);
                    float v = acc[r][s] + Bs[j];
                    if (relu) v = fmaxf(v, 0.f);
                    if (padstore || j < dout)
                        C[(size_t)row * ldc + j] = v;
                }
            }
        }
    }
}

// ---------------- host ------------------------------------------------------
static inline size_t smbytes(int din, int PN)
{
    int din4 = (din + 3) & ~3;
    return (size_t)(din4 * PN + PN) * sizeof(float);
}

extern "C" void kernel_launch(void* const* d_in, const int* in_sizes, int n_in,
                              void* d_out, int out_size)
{
    const float* t    = (const float*)d_in[0];
    const float* x    = (const float*)d_in[1];
    const float* ofx  = (const float*)d_in[2];
    const int*   src  = (const int*)d_in[3];
    const int*   tgt  = (const int*)d_in[4];
    const float* RW0  = (const float*)d_in[5];
    const float* Rb0  = (const float*)d_in[6];
    const float* RW1  = (const float*)d_in[7];
    const float* Rb1  = (const float*)d_in[8];
    const float* RW2  = (const float*)d_in[9];
    const float* Rb2  = (const float*)d_in[10];
    const float* RW3  = (const float*)d_in[11];
    const float* Rb3  = (const float*)d_in[12];
    const float* RW4  = (const float*)d_in[13];
    const float* Rb4  = (const float*)d_in[14];
    const float* OW0  = (const float*)d_in[15];
    const float* Ob0  = (const float*)d_in[16];
    const float* OW1  = (const float*)d_in[17];
    const float* Ob1  = (const float*)d_in[18];
    float* out = (float*)d_out;

    const int M = in_sizes[3];      // n edges
    const int N = in_sizes[1] / 4;  // n nodes

    float *bufA, *bufB, *ep;
    cudaGetSymbolAddress((void**)&bufA, g_bufA);
    cudaGetSymbolAddress((void**)&bufB, g_bufB);
    cudaGetSymbolAddress((void**)&ep,   g_eprime);

    int nsm = 148;
    cudaDeviceGetAttribute(&nsm, cudaDevAttrMultiProcessorCount, 0);
    const int nblk = 2 * nsm;

    cudaFuncSetAttribute(gemm_kernel<5>, cudaFuncAttributeMaxDynamicSharedMemorySize, 112 * 1024);
    cudaFuncSetAttribute(gemm_kernel<4>, cudaFuncAttributeMaxDynamicSharedMemorySize, 112 * 1024);
    cudaFuncSetAttribute(gemm_kernel<2>, cudaFuncAttributeMaxDynamicSharedMemorySize, 112 * 1024);
    cudaFuncSetAttribute(gemm_kernel<1>, cudaFuncAttributeMaxDynamicSharedMemorySize, 112 * 1024);

    // zero E'
    zero_kernel<<<(N * 64 + 255) / 256, 256>>>(ep, N * 64);
    // R' gather into bufA (stride 16, zero-padded cols 13..15)
    gather_kernel<<<(M + 255) / 256, 256>>>(x, ofx, src, tgt, t, bufA, M);

    // edge MLP (intermediates stride 160, padded cols written as exact zeros)
    gemm_kernel<5><<<nblk, 256, smbytes(13, 160)>>>(bufA, 16,  RW0, Rb0, bufB, 160, M, 13,  150, 1, 1);
    gemm_kernel<5><<<nblk, 256, smbytes(150, 160)>>>(bufB, 160, RW1, Rb1, bufA, 160, M, 150, 150, 1, 1);
    gemm_kernel<5><<<nblk, 256, smbytes(150, 160)>>>(bufA, 160, RW2, Rb2, bufB, 160, M, 150, 150, 1, 1);
    gemm_kernel<5><<<nblk, 256, smbytes(150, 160)>>>(bufB, 160, RW3, Rb3, bufA, 160, M, 150, 150, 1, 1);
    // L5: compact output (stride 64), only real 50 cols written
    gemm_kernel<2><<<nblk, 256, smbytes(150, 64)>>>(bufA, 160, RW4, Rb4, bufB, 64, M, 150, 50, 0, 0);

    // segment-sum (scatter add): E (bufB, stride 64, cols 0..49) -> E' [N,64]
    scatter_kernel<<<(M * 32 + 255) / 256, 256>>>(bufB, tgt, ep, M);

    // node MLP
    gemm_kernel<4><<<nblk, 256, smbytes(50, 128)>>>(ep,   64,  OW0, Ob0, bufA, 128, N, 50,  100, 1, 1);
    gemm_kernel<1><<<nblk, 256, smbytes(100, 32)>>>(bufA, 128, OW1, Ob1, out,  4,   N, 100, 4,   0, 0);
}

// round 5
// speedup vs baseline: 1.3898x; 1.3898x over previous
#include <cuda_runtime.h>
#include <cuda_bf16.h>
#include <mma.h>
#include <cstdint>
#include <cstddef>

using namespace nvcuda;

// ===================== scratch (no allocations allowed) =====================
#define MAX_EDGES 2000000
#define MAX_NODES 100000

__device__ __align__(128) float g_bufA[(size_t)MAX_EDGES * 160];
__device__ __align__(128) float g_bufB[(size_t)MAX_EDGES * 160];
__device__ __align__(128) float g_rp[(size_t)MAX_EDGES * 16];
__device__ float g_eprime[(size_t)MAX_NODES * 64];
__device__ __align__(128) __nv_bfloat16 g_wstage[262144];   // 512 KB

// ===================== weight prep: pad + bias-fold + hi/lo split ===========
// Produces smem-ready image: plane0 = hi [KD][WSTR], plane1 = lo [KD][WSTR].
// Row bias_row (>= din) carries the bias (activation col one_col is forced 1).
__global__ void prep_w(const float* __restrict__ W, const float* __restrict__ bias,
                       int din, int dout, int KD, int WSTR, int bias_row,
                       __nv_bfloat16* __restrict__ dst)
{
    int idx = blockIdx.x * blockDim.x + threadIdx.x;
    int tot = KD * WSTR;
    if (idx >= tot) return;
    int k = idx / WSTR, n = idx % WSTR;
    float v = 0.f;
    if (n < dout) {
        if (k < din) v = W[(size_t)k * dout + n];
        else if (k == bias_row) v = bias[n];
    }
    __nv_bfloat16 h = __float2bfloat16(v);
    __nv_bfloat16 l = __float2bfloat16(v - __bfloat162float(h));
    dst[idx] = h;
    dst[tot + idx] = l;
}

// ===================== gather: R'[M,16] fp32 ================================
// cols: xs0..3, os0..1, xt0..3, ot0..1, t, 0(one-col, set by stager), 0, 0
__global__ void gather_kernel(const float* __restrict__ x,
                              const float* __restrict__ ofx,
                              const int* __restrict__ src,
                              const int* __restrict__ tgt,
                              const float* __restrict__ t,
                              float* __restrict__ out, int M)
{
    int e = blockIdx.x * blockDim.x + threadIdx.x;
    if (e >= M) return;
    int s = src[e], g = tgt[e];
    float4 xs = *(const float4*)(x + (size_t)4 * s);
    float2 os = *(const float2*)(ofx + (size_t)2 * s);
    float4 xt = *(const float4*)(x + (size_t)4 * g);
    float2 ot = *(const float2*)(ofx + (size_t)2 * g);
    float tv = t[0];
    float4* o = (float4*)(out + (size_t)e * 16);
    o[0] = xs;
    o[1] = make_float4(os.x, os.y, xt.x, xt.y);
    o[2] = make_float4(xt.z, xt.w, ot.x, ot.y);
    o[3] = make_float4(tv, 0.f, 0.f, 0.f);
}

__global__ void zero_kernel(float* __restrict__ p, int n)
{
    int i = blockIdx.x * blockDim.x + threadIdx.x;
    if (i < n) p[i] = 0.f;
}

// scatter-add: E[M,64] f32 (cols 0..49 real) -> ep[N,64]
__global__ void scatter_kernel(const float* __restrict__ E,
                               const int* __restrict__ tgt,
                               float* __restrict__ ep, int M)
{
    int idx = blockIdx.x * blockDim.x + threadIdx.x;
    int e = idx >> 5;
    if (e >= M) return;
    int lane = idx & 31;
    int tg = __ldg(tgt + e);
    const float* Er = E + (size_t)e * 64;
    float* dst = ep + (size_t)tg * 64;
    atomicAdd(dst + lane, Er[lane]);
    if (lane < 18) atomicAdd(dst + lane + 32, Er[lane + 32]);
}

// ===================== wmma bf16 hi/lo split layer ==========================
// out[M, NT*16] = act(in[M, KT*16] * Wsplit + bias-row), fp32 accum.
// 3-term split per k-step: Ah*Wh + Ah*Wl + Al*Wh.
// 256 threads: warp grid 4 (m) x 2 (n); warp tile 16 x (NTW*16). M tile = 64.
template <int KT, int NT, int NTW, bool RELU>
__global__ __launch_bounds__(256, 1)
void wmma_layer(const float* __restrict__ in,
                const __nv_bfloat16* __restrict__ wimg,
                float* __restrict__ out, int one_col, int M)
{
    constexpr int KD = KT * 16;
    constexpr int ND = NT * 16;
    constexpr int ASTR = KD + 8;
    constexpr int WSTR = ND + 8;
    constexpr int WPLANE = KD * WSTR;            // elems per plane
    constexpr int WBYTES = 2 * WPLANE * 2;

    extern __shared__ unsigned char smem[];
    __nv_bfloat16* Wh = (__nv_bfloat16*)smem;
    __nv_bfloat16* Wl = Wh + WPLANE;
    __nv_bfloat16* Ah = (__nv_bfloat16*)(smem + WBYTES);
    __nv_bfloat16* Al = Ah + 64 * ASTR;

    const int tid = threadIdx.x;
    const int wid = tid >> 5;
    const int warp_m = wid & 3;
    const int warp_n = wid >> 2;

    // weights -> smem (straight copy of prepped image)
    {
        const uint4* s4 = (const uint4*)wimg;
        uint4* d4 = (uint4*)smem;
        for (int i = tid; i < WBYTES / 16; i += 256) d4[i] = s4[i];
    }
    __syncthreads();

    const int ntiles = (M + 63) >> 6;

    for (int tile = blockIdx.x; tile < ntiles; tile += gridDim.x) {
        const size_t row0 = (size_t)tile << 6;

        // ---- stage A: fp32 -> bf16 hi/lo planes in smem --------------------
        for (int i = tid; i < 64 * (KD / 4); i += 256) {
            int row = i / (KD / 4);
            int c4 = (i - row * (KD / 4)) * 4;
            size_t rr = row0 + row; if (rr >= (size_t)M) rr = (size_t)M - 1;
            float4 v = *(const float4*)(in + rr * KD + c4);
            float vv[4] = {v.x, v.y, v.z, v.w};
            if (one_col >= c4 && one_col < c4 + 4) vv[one_col - c4] = 1.0f;
            uint32_t hp[2], lp[2];
#pragma unroll
            for (int q = 0; q < 2; q++) {
                __nv_bfloat16 h0 = __float2bfloat16(vv[2*q]);
                __nv_bfloat16 h1 = __float2bfloat16(vv[2*q+1]);
                __nv_bfloat16 l0 = __float2bfloat16(vv[2*q]   - __bfloat162float(h0));
                __nv_bfloat16 l1 = __float2bfloat16(vv[2*q+1] - __bfloat162float(h1));
                hp[q] = (uint32_t)__bfloat16_as_ushort(h0) | ((uint32_t)__bfloat16_as_ushort(h1) << 16);
                lp[q] = (uint32_t)__bfloat16_as_ushort(l0) | ((uint32_t)__bfloat16_as_ushort(l1) << 16);
            }
            *(uint2*)(Ah + row * ASTR + c4) = make_uint2(hp[0], hp[1]);
            *(uint2*)(Al + row * ASTR + c4) = make_uint2(lp[0], lp[1]);
        }
        __syncthreads();

        // ---- compute --------------------------------------------------------
        wmma::fragment<wmma::accumulator, 16, 16, 16, float> acc[NTW];
#pragma unroll
        for (int nt = 0; nt < NTW; nt++) wmma::fill_fragment(acc[nt], 0.f);

#pragma unroll
        for (int k0 = 0; k0 < KT; k0++) {
            wmma::fragment<wmma::matrix_a, 16, 16, 16, __nv_bfloat16, wmma::row_major> aH, aL;
            wmma::load_matrix_sync(aH, Ah + (warp_m * 16) * ASTR + k0 * 16, ASTR);
            wmma::load_matrix_sync(aL, Al + (warp_m * 16) * ASTR + k0 * 16, ASTR);
#pragma unroll
            for (int nt = 0; nt < NTW; nt++) {
                int n0 = (warp_n * NTW + nt) * 16;
                wmma::fragment<wmma::matrix_b, 16, 16, 16, __nv_bfloat16, wmma::row_major> bH, bL;
                wmma::load_matrix_sync(bH, Wh + (k0 * 16) * WSTR + n0, WSTR);
                wmma::load_matrix_sync(bL, Wl + (k0 * 16) * WSTR + n0, WSTR);
                wmma::mma_sync(acc[nt], aH, bH, acc[nt]);
                wmma::mma_sync(acc[nt], aH, bL, acc[nt]);
                wmma::mma_sync(acc[nt], aL, bH, acc[nt]);
            }
        }

        if (RELU) {
#pragma unroll
            for (int nt = 0; nt < NTW; nt++)
#pragma unroll
                for (int e = 0; e < acc[0].num_elements; e++)
                    acc[nt].x[e] = fmaxf(acc[nt].x[e], 0.f);
        }

        // ---- store ----------------------------------------------------------
        bool tail = (row0 + 64 > (size_t)M);
        if (!tail) {
#pragma unroll
            for (int nt = 0; nt < NTW; nt++) {
                int n0 = (warp_n * NTW + nt) * 16;
                wmma::store_matrix_sync(out + (row0 + warp_m * 16) * ND + n0,
                                        acc[nt], ND, wmma::mem_row_major);
            }
        } else {
            __syncthreads();                 // A reads done; reuse as scratch
            float* scr = (float*)(smem + WBYTES);
#pragma unroll
            for (int nt = 0; nt < NTW; nt++) {
                int n0 = (warp_n * NTW + nt) * 16;
                wmma::store_matrix_sync(scr + (warp_m * 16) * ND + n0,
                                        acc[nt], ND, wmma::mem_row_major);
            }
            __syncthreads();
            for (int i = tid; i < 64 * ND; i += 256) {
                int r = i / ND, c = i - r * ND;
                size_t rr = row0 + r;
                if (rr < (size_t)M) out[rr * ND + c] = scr[i];
            }
        }
        __syncthreads();                     // protect A/scratch before next stage
    }
}

// ===================== SIMT GEMM (node MLP) =================================
template <int NS>
__global__ __launch_bounds__(256, 2)
void gemm_kernel(const float* __restrict__ A, int lda,
                 const float* __restrict__ W, const float* __restrict__ B,
                 float* __restrict__ C, int ldc,
                 int M, int din, int dout, int relu, int padstore)
{
    constexpr int PN = NS * 32;
    extern __shared__ float sm[];
    float* Ws = sm;
    float* Bs = Ws + ((din + 3) & ~3) * PN;
    const int tid = threadIdx.x;
    const int din4 = (din + 3) & ~3;
    for (int idx = tid; idx < din4 * PN; idx += 256) {
        int k = idx / PN, j = idx - k * PN;
        Ws[idx] = (k < din && j < dout) ? W[(size_t)k * dout + j] : 0.f;
    }
    for (int j = tid; j < PN; j += 256) Bs[j] = (j < dout) ? B[j] : 0.f;
    __syncthreads();
    const int lane = tid & 31;
    const int gwarp = blockIdx.x * 8 + (tid >> 5);
    const int nwarp = gridDim.x * 8;
    for (int sidx = gwarp; sidx < (M + 7) >> 3; sidx += nwarp) {
        const int row0 = sidx << 3;
        const float* ap[8];
#pragma unroll
        for (int r = 0; r < 8; r++) {
            int rr = row0 + r; if (rr > M - 1) rr = M - 1;
            ap[r] = A + (size_t)rr * lda;
        }
        float acc[8][NS];
#pragma unroll
        for (int r = 0; r < 8; r++)
#pragma unroll
            for (int s = 0; s < NS; s++) acc[r][s] = 0.f;
#pragma unroll 2
        for (int k = 0; k < din4; k += 4) {
            float4 a[8];
#pragma unroll
            for (int r = 0; r < 8; r++) a[r] = *(const float4*)(ap[r] + k);
#pragma unroll
            for (int kk = 0; kk < 4; kk++) {
                float wv[NS];
#pragma unroll
                for (int s = 0; s < NS; s++) wv[s] = Ws[(k + kk) * PN + lane + (s << 5)];
#pragma unroll
                for (int r = 0; r < 8; r++) {
                    float av = (kk == 0) ? a[r].x : (kk == 1) ? a[r].y : (kk == 2) ? a[r].z : a[r].w;
#pragma unroll
                    for (int s = 0; s < NS; s++) acc[r][s] = fmaf(av, wv[s], acc[r][s]);
                }
            }
        }
#pragma unroll
        for (int r = 0; r < 8; r++) {
            int row = row0 + r;
            if (row < M) {
#pragma unroll
                for (int s = 0; s < NS; s++) {
                    int j = lane + (s << 5);
                    float v = acc[r][s] + Bs[j];
                    if (relu) v = fmaxf(v, 0.f);
                    if (padstore || j < dout) C[(size_t)row * ldc + j] = v;
                }
            }
        }
    }
}

// ===================== host ==================================================
static inline size_t smbytes(int din, int PN)
{
    int din4 = (din + 3) & ~3;
    return (size_t)(din4 * PN + PN) * sizeof(float);
}

extern "C" void kernel_launch(void* const* d_in, const int* in_sizes, int n_in,
                              void* d_out, int out_size)
{
    const float* t   = (const float*)d_in[0];
    const float* x   = (const float*)d_in[1];
    const float* ofx = (const float*)d_in[2];
    const int* src   = (const int*)d_in[3];
    const int* tgt   = (const int*)d_in[4];
    const float* RW[5] = {(const float*)d_in[5], (const float*)d_in[7], (const float*)d_in[9],
                          (const float*)d_in[11], (const float*)d_in[13]};
    const float* Rb[5] = {(const float*)d_in[6], (const float*)d_in[8], (const float*)d_in[10],
                          (const float*)d_in[12], (const float*)d_in[14]};
    const float* OW0 = (const float*)d_in[15];
    const float* Ob0 = (const float*)d_in[16];
    const float* OW1 = (const float*)d_in[17];
    const float* Ob1 = (const float*)d_in[18];
    float* out = (float*)d_out;

    const int M = in_sizes[3];
    const int N = in_sizes[1] / 4;

    float *bufA, *bufB, *rp, *ep;
    __nv_bfloat16* wst;
    cudaGetSymbolAddress((void**)&bufA, g_bufA);
    cudaGetSymbolAddress((void**)&bufB, g_bufB);
    cudaGetSymbolAddress((void**)&rp,   g_rp);
    cudaGetSymbolAddress((void**)&ep,   g_eprime);
    cudaGetSymbolAddress((void**)&wst,  g_wstage);

    int nsm = 148;
    cudaDeviceGetAttribute(&nsm, cudaDevAttrMultiProcessorCount, 0);

    // ---- weight prep (smem images) -----------------------------------------
    // layers: 0: K16->N160 ; 1-3: K160->N160 ; 4: K160->N64
    // plane elems: L0 16*168=2688 ; L1-3 160*168=26880 ; L4 160*72=11520
    const size_t woff[5] = {0, 2*2688, 2*2688 + 2*26880, 2*2688 + 4*26880, 2*2688 + 6*26880};
    const int wdin[5]  = {13, 150, 150, 150, 150};
    const int wdout[5] = {150, 150, 150, 150, 50};
    const int wKD[5]   = {16, 160, 160, 160, 160};
    const int wWSTR[5] = {168, 168, 168, 168, 72};
    const int wbrow[5] = {13, 150, 150, 150, 150};
    for (int i = 0; i < 5; i++) {
        int tot = wKD[i] * wWSTR[i];
        prep_w<<<(tot + 255) / 256, 256>>>(RW[i], Rb[i], wdin[i], wdout[i],
                                           wKD[i], wWSTR[i], wbrow[i], wst + woff[i]);
    }

    zero_kernel<<<(N * 64 + 255) / 256, 256>>>(ep, N * 64);
    gather_kernel<<<(M + 255) / 256, 256>>>(x, ofx, src, tgt, t, rp, M);

    // ---- smem sizes ----------------------------------------------------------
    // WBYTES + max(A planes, tail scratch 64*ND*4)
    auto amax = [](int KD, int ND) {
        size_t a = (size_t)2 * 64 * (KD + 8) * 2;
        size_t s = (size_t)64 * ND * 4;
        return a > s ? a : s;
    };
    const size_t sm0 = (size_t)2 * 2688 * 2  + amax(16, 160);   // 10752 + 40960
    const size_t sm1 = (size_t)2 * 26880 * 2 + amax(160, 160);  // 107520 + 43008
    const size_t sm4 = (size_t)2 * 11520 * 2 + amax(160, 64);   // 46080 + 43008
    cudaFuncSetAttribute(wmma_layer<1, 10, 5, true>,  cudaFuncAttributeMaxDynamicSharedMemorySize, (int)sm0);
    cudaFuncSetAttribute(wmma_layer<10, 10, 5, true>, cudaFuncAttributeMaxDynamicSharedMemorySize, (int)sm1);
    cudaFuncSetAttribute(wmma_layer<10, 4, 2, false>, cudaFuncAttributeMaxDynamicSharedMemorySize, (int)sm4);

    // ---- edge MLP -------------------------------------------------------------
    wmma_layer<1, 10, 5, true> <<<nsm, 256, sm0>>>(rp,   wst + woff[0], bufA, 13,  M);
    wmma_layer<10, 10, 5, true><<<nsm, 256, sm1>>>(bufA, wst + woff[1], bufB, 150, M);
    wmma_layer<10, 10, 5, true><<<nsm, 256, sm1>>>(bufB, wst + woff[2], bufA, 150, M);
    wmma_layer<10, 10, 5, true><<<nsm, 256, sm1>>>(bufA, wst + woff[3], bufB, 150, M);
    wmma_layer<10, 4, 2, false><<<nsm, 256, sm4>>>(bufB, wst + woff[4], bufA, 150, M);

    // ---- segment sum ------------------------------------------------------------
    scatter_kernel<<<(M * 32 + 255) / 256, 256>>>(bufA, tgt, ep, M);

    // ---- node MLP ----------------------------------------------------------------
    cudaFuncSetAttribute(gemm_kernel<4>, cudaFuncAttributeMaxDynamicSharedMemorySize, 112 * 1024);
    cudaFuncSetAttribute(gemm_kernel<1>, cudaFuncAttributeMaxDynamicSharedMemorySize, 112 * 1024);
    float* nb = rp;   // reuse [N,128]
    gemm_kernel<4><<<2 * nsm, 256, smbytes(50, 128)>>>(ep, 64, OW0, Ob0, nb, 128, N, 50, 100, 1, 1);
    gemm_kernel<1><<<2 * nsm, 256, smbytes(100, 32)>>>(nb, 128, OW1, Ob1, out, 4, N, 100, 4, 0, 0);
}

// round 6
// speedup vs baseline: 2.0628x; 1.4843x over previous
#include <cuda_runtime.h>
#include <cuda_bf16.h>
#include <mma.h>
#include <cstdint>
#include <cstddef>

using namespace nvcuda;

// ===================== scratch (no allocations allowed) =====================
#define MAX_EDGES 2000000
#define MAX_NODES 100000
#define SLACK 128

__device__ __align__(128) __nv_bfloat16 g_rpH[(size_t)(MAX_EDGES + SLACK) * 16];
__device__ __align__(128) __nv_bfloat16 g_rpL[(size_t)(MAX_EDGES + SLACK) * 16];
__device__ __align__(128) __nv_bfloat16 g_Xh[(size_t)(MAX_EDGES + SLACK) * 160];
__device__ __align__(128) __nv_bfloat16 g_Xl[(size_t)(MAX_EDGES + SLACK) * 160];
__device__ __align__(128) __nv_bfloat16 g_Yh[(size_t)(MAX_EDGES + SLACK) * 160];
__device__ __align__(128) __nv_bfloat16 g_Yl[(size_t)(MAX_EDGES + SLACK) * 160];
__device__ float g_eprime[(size_t)MAX_NODES * 64];
__device__ __align__(128) __nv_bfloat16 g_wstage[262144];

// ===================== cp.async helpers ======================================
__device__ __forceinline__ uint32_t smem_u32(const void* p) {
    uint32_t a;
    asm("{ .reg .u64 t; cvta.to.shared.u64 t, %1; cvt.u32.u64 %0, t; }" : "=r"(a) : "l"(p));
    return a;
}
__device__ __forceinline__ void cpa16(uint32_t dst, const void* src) {
    asm volatile("cp.async.cg.shared.global [%0], [%1], 16;" :: "r"(dst), "l"(src));
}
#define CP_COMMIT() asm volatile("cp.async.commit_group;" ::: "memory")
#define CP_WAIT1()  asm volatile("cp.async.wait_group 1;" ::: "memory")

// ===================== weight prep: pad + bias-fold + hi/lo split ===========
__global__ void prep_w(const float* __restrict__ W, const float* __restrict__ bias,
                       int din, int dout, int KD, int WSTR, int bias_row,
                       __nv_bfloat16* __restrict__ dst)
{
    int idx = blockIdx.x * blockDim.x + threadIdx.x;
    int tot = KD * WSTR;
    if (idx >= tot) return;
    int k = idx / WSTR, n = idx % WSTR;
    float v = 0.f;
    if (n < dout) {
        if (k < din) v = W[(size_t)k * dout + n];
        else if (k == bias_row) v = bias[n];
    }
    __nv_bfloat16 h = __float2bfloat16(v);
    __nv_bfloat16 l = __float2bfloat16(v - __bfloat162float(h));
    dst[idx] = h;
    dst[tot + idx] = l;
}

// ===================== gather: R'[M,16] bf16 hi/lo (col13 = 1 for bias) =====
__global__ void gather_kernel(const float* __restrict__ x,
                              const float* __restrict__ ofx,
                              const int* __restrict__ src,
                              const int* __restrict__ tgt,
                              const float* __restrict__ t,
                              __nv_bfloat16* __restrict__ oh,
                              __nv_bfloat16* __restrict__ ol, int M)
{
    int e = blockIdx.x * blockDim.x + threadIdx.x;
    if (e >= M) return;
    int s = src[e], g = tgt[e];
    float v[16];
    float4 xs = *(const float4*)(x + (size_t)4 * s);
    float2 os = *(const float2*)(ofx + (size_t)2 * s);
    float4 xt = *(const float4*)(x + (size_t)4 * g);
    float2 ot = *(const float2*)(ofx + (size_t)2 * g);
    v[0]=xs.x; v[1]=xs.y; v[2]=xs.z; v[3]=xs.w; v[4]=os.x; v[5]=os.y;
    v[6]=xt.x; v[7]=xt.y; v[8]=xt.z; v[9]=xt.w; v[10]=ot.x; v[11]=ot.y;
    v[12]=t[0]; v[13]=1.0f; v[14]=0.f; v[15]=0.f;
    uint32_t wh[8], wl[8];
#pragma unroll
    for (int i = 0; i < 8; i++) {
        __nv_bfloat16 h0 = __float2bfloat16(v[2*i]);
        __nv_bfloat16 h1 = __float2bfloat16(v[2*i+1]);
        __nv_bfloat16 l0 = __float2bfloat16(v[2*i]   - __bfloat162float(h0));
        __nv_bfloat16 l1 = __float2bfloat16(v[2*i+1] - __bfloat162float(h1));
        wh[i] = (uint32_t)__bfloat16_as_ushort(h0) | ((uint32_t)__bfloat16_as_ushort(h1) << 16);
        wl[i] = (uint32_t)__bfloat16_as_ushort(l0) | ((uint32_t)__bfloat16_as_ushort(l1) << 16);
    }
    uint4* ph = (uint4*)(oh + (size_t)e * 16);
    uint4* pl = (uint4*)(ol + (size_t)e * 16);
    ph[0] = make_uint4(wh[0], wh[1], wh[2], wh[3]);
    ph[1] = make_uint4(wh[4], wh[5], wh[6], wh[7]);
    pl[0] = make_uint4(wl[0], wl[1], wl[2], wl[3]);
    pl[1] = make_uint4(wl[4], wl[5], wl[6], wl[7]);
}

__global__ void zero_kernel(float* __restrict__ p, int n)
{
    int i = blockIdx.x * blockDim.x + threadIdx.x;
    if (i < n) p[i] = 0.f;
}

// scatter-add: E[M,64] f32 -> ep[N,64]
__global__ void scatter_kernel(const float* __restrict__ E,
                               const int* __restrict__ tgt,
                               float* __restrict__ ep, int M)
{
    int idx = blockIdx.x * blockDim.x + threadIdx.x;
    int e = idx >> 5;
    if (e >= M) return;
    int lane = idx & 31;
    int tg = __ldg(tgt + e);
    const float* Er = E + (size_t)e * 64;
    float* dst = ep + (size_t)tg * 64;
    atomicAdd(dst + lane, Er[lane]);
    if (lane < 18) atomicAdd(dst + lane + 32, Er[lane + 32]);
}

// ===================== fused wmma layer ======================================
// B fragments register-resident; A tiles (64 rows) double-buffered via cp.async.
// OUTMODE 0: relu -> bf16 hi/lo planes (width ND), col onecol forced to 1.0
// OUTMODE 1: raw f32 (width ND)
template <int KT, int ND, int WN, int WM, int OUTMODE>
__global__ __launch_bounds__(32 * WN * WM, 1)
void fused_layer(const __nv_bfloat16* __restrict__ inH,
                 const __nv_bfloat16* __restrict__ inL,
                 const __nv_bfloat16* __restrict__ wimg,
                 __nv_bfloat16* __restrict__ outH,
                 __nv_bfloat16* __restrict__ outL,
                 float* __restrict__ outF,
                 int M, int onecol)
{
    constexpr int THREADS = 32 * WN * WM;
    constexpr int KD = KT * 16;
    constexpr int ASTR = KD + 8;
    constexpr int WSTR = ND + 8;
    constexpr int WPLANE = KD * WSTR;
    constexpr int ABUF_ELE = 2 * 64 * ASTR;         // hi+lo planes per buffer
    constexpr int CPR = KD / 8;                     // 16B chunks per row
    constexpr int NCHUNK = 64 * CPR * 2;            // per buffer

    extern __shared__ unsigned char smem[];
    __nv_bfloat16* Wh = (__nv_bfloat16*)smem;
    __nv_bfloat16* Wl = Wh + WPLANE;
    __nv_bfloat16* A0 = Wl + WPLANE;
    float* scr = (float*)(A0 + 2 * ABUF_ELE);

    const int tid = threadIdx.x;
    const int wid = tid >> 5;
    const int lane = tid & 31;
    const int warp_n = wid % WN;
    const int warp_m = wid / WN;
    const uint32_t a_u32 = smem_u32(A0);

    // weights -> smem
    {
        const uint4* s4 = (const uint4*)wimg;
        uint4* d4 = (uint4*)smem;
        for (int i = tid; i < (2 * WPLANE * 2) / 16; i += THREADS) d4[i] = s4[i];
    }
    __syncthreads();

    // hoist B fragments into registers
    wmma::fragment<wmma::matrix_b, 16, 16, 16, __nv_bfloat16, wmma::row_major> bH[KT], bL[KT];
#pragma unroll
    for (int k0 = 0; k0 < KT; k0++) {
        wmma::load_matrix_sync(bH[k0], Wh + (k0 * 16) * WSTR + warp_n * 16, WSTR);
        wmma::load_matrix_sync(bL[k0], Wl + (k0 * 16) * WSTR + warp_n * 16, WSTR);
    }

    const int ntiles = (M + 63) >> 6;
    float* scrw = scr + wid * 256;

    // stage tile into buffer b (pure cp.async copy; rows clamped)
    auto stage = [&](int b, int tile) {
        const int row0 = tile << 6;
        const uint32_t abase = a_u32 + b * (ABUF_ELE * 2);
        for (int i = tid; i < NCHUNK; i += THREADS) {
            int plane = i / (64 * CPR);
            int rem = i - plane * (64 * CPR);
            int row = rem / CPR, ch = rem - row * CPR;
            int rsrc = row0 + row; if (rsrc >= M) rsrc = M - 1;
            const __nv_bfloat16* s = (plane ? inL : inH) + (size_t)rsrc * KD + ch * 8;
            cpa16(abase + plane * (64 * ASTR * 2) + (row * ASTR + ch * 8) * 2, s);
        }
        CP_COMMIT();
    };

    int tile = blockIdx.x;
    if (tile < ntiles) stage(0, tile); else CP_COMMIT();
    int buf = 0;

    for (; tile < ntiles; tile += gridDim.x) {
        const int nxt = tile + gridDim.x;
        stage(buf ^ 1, nxt < ntiles ? nxt : tile);
        CP_WAIT1();
        __syncthreads();

        const __nv_bfloat16* Ah = A0 + buf * ABUF_ELE;
        const __nv_bfloat16* Al = Ah + 64 * ASTR;
        const size_t row0 = (size_t)tile << 6;

        for (int sub = warp_m; sub < 4; sub += WM) {
            wmma::fragment<wmma::accumulator, 16, 16, 16, float> acc;
            wmma::fill_fragment(acc, 0.f);
#pragma unroll
            for (int k0 = 0; k0 < KT; k0++) {
                wmma::fragment<wmma::matrix_a, 16, 16, 16, __nv_bfloat16, wmma::row_major> aH, aL;
                wmma::load_matrix_sync(aH, Ah + (sub * 16) * ASTR + k0 * 16, ASTR);
                wmma::load_matrix_sync(aL, Al + (sub * 16) * ASTR + k0 * 16, ASTR);
                wmma::mma_sync(acc, aH, bH[k0], acc);
                wmma::mma_sync(acc, aH, bL[k0], acc);
                wmma::mma_sync(acc, aL, bH[k0], acc);
            }
            wmma::store_matrix_sync(scrw, acc, 16, wmma::mem_row_major);
            __syncwarp();

            const int r = lane >> 1, c0 = (lane & 1) * 8;
            const float* s = scrw + r * 16 + c0;
            const int gc0 = warp_n * 16 + c0;
            const size_t grow = row0 + sub * 16 + r;
            if (OUTMODE == 0) {
                uint32_t hh[4], ll[4];
#pragma unroll
                for (int q = 0; q < 4; q++) {
                    float v0 = fmaxf(s[2*q], 0.f);
                    float v1 = fmaxf(s[2*q+1], 0.f);
                    if (gc0 + 2*q == onecol)     v0 = 1.0f;
                    if (gc0 + 2*q + 1 == onecol) v1 = 1.0f;
                    __nv_bfloat16 h0 = __float2bfloat16(v0);
                    __nv_bfloat16 h1 = __float2bfloat16(v1);
                    __nv_bfloat16 l0 = __float2bfloat16(v0 - __bfloat162float(h0));
                    __nv_bfloat16 l1 = __float2bfloat16(v1 - __bfloat162float(h1));
                    hh[q] = (uint32_t)__bfloat16_as_ushort(h0) | ((uint32_t)__bfloat16_as_ushort(h1) << 16);
                    ll[q] = (uint32_t)__bfloat16_as_ushort(l0) | ((uint32_t)__bfloat16_as_ushort(l1) << 16);
                }
                *(uint4*)(outH + grow * ND + gc0) = make_uint4(hh[0], hh[1], hh[2], hh[3]);
                *(uint4*)(outL + grow * ND + gc0) = make_uint4(ll[0], ll[1], ll[2], ll[3]);
            } else {
                float* o = outF + grow * ND + gc0;
                *(float4*)(o)     = make_float4(s[0], s[1], s[2], s[3]);
                *(float4*)(o + 4) = make_float4(s[4], s[5], s[6], s[7]);
            }
            __syncwarp();
        }
        __syncthreads();
        buf ^= 1;
    }
}

// ===================== SIMT GEMM (node MLP) =================================
template <int NS>
__global__ __launch_bounds__(256, 2)
void gemm_kernel(const float* __restrict__ A, int lda,
                 const float* __restrict__ W, const float* __restrict__ B,
                 float* __restrict__ C, int ldc,
                 int M, int din, int dout, int relu, int padstore)
{
    constexpr int PN = NS * 32;
    extern __shared__ float sm[];
    float* Ws = sm;
    float* Bs = Ws + ((din + 3) & ~3) * PN;
    const int tid = threadIdx.x;
    const int din4 = (din + 3) & ~3;
    for (int idx = tid; idx < din4 * PN; idx += 256) {
        int k = idx / PN, j = idx - k * PN;
        Ws[idx] = (k < din && j < dout) ? W[(size_t)k * dout + j] : 0.f;
    }
    for (int j = tid; j < PN; j += 256) Bs[j] = (j < dout) ? B[j] : 0.f;
    __syncthreads();
    const int lane = tid & 31;
    const int gwarp = blockIdx.x * 8 + (tid >> 5);
    const int nwarp = gridDim.x * 8;
    for (int sidx = gwarp; sidx < (M + 7) >> 3; sidx += nwarp) {
        const int row0 = sidx << 3;
        const float* ap[8];
#pragma unroll
        for (int r = 0; r < 8; r++) {
            int rr = row0 + r; if (rr > M - 1) rr = M - 1;
            ap[r] = A + (size_t)rr * lda;
        }
        float acc[8][NS];
#pragma unroll
        for (int r = 0; r < 8; r++)
#pragma unroll
            for (int s = 0; s < NS; s++) acc[r][s] = 0.f;
#pragma unroll 2
        for (int k = 0; k < din4; k += 4) {
            float4 a[8];
#pragma unroll
            for (int r = 0; r < 8; r++) a[r] = *(const float4*)(ap[r] + k);
#pragma unroll
            for (int kk = 0; kk < 4; kk++) {
                float wv[NS];
#pragma unroll
                for (int s = 0; s < NS; s++) wv[s] = Ws[(k + kk) * PN + lane + (s << 5)];
#pragma unroll
                for (int r = 0; r < 8; r++) {
                    float av = (kk == 0) ? a[r].x : (kk == 1) ? a[r].y : (kk == 2) ? a[r].z : a[r].w;
#pragma unroll
                    for (int s = 0; s < NS; s++) acc[r][s] = fmaf(av, wv[s], acc[r][s]);
                }
            }
        }
#pragma unroll
        for (int r = 0; r < 8; r++) {
            int row = row0 + r;
            if (row < M) {
#pragma unroll
                for (int s = 0; s < NS; s++) {
                    int j = lane + (s << 5);
                    float v = acc[r][s] + Bs[j];
                    if (relu) v = fmaxf(v, 0.f);
                    if (padstore || j < dout) C[(size_t)row * ldc + j] = v;
                }
            }
        }
    }
}

// ===================== host ==================================================
static inline size_t smbytes(int din, int PN)
{
    int din4 = (din + 3) & ~3;
    return (size_t)(din4 * PN + PN) * sizeof(float);
}
static inline size_t fl_smem(int KT, int ND, int nwarp)
{
    int KD = KT * 16, ASTR = KD + 8, WSTR = ND + 8;
    return (size_t)(2 * KD * WSTR * 2) + (size_t)(2 * 2 * 64 * ASTR * 2) + (size_t)nwarp * 1024;
}

extern "C" void kernel_launch(void* const* d_in, const int* in_sizes, int n_in,
                              void* d_out, int out_size)
{
    const float* t   = (const float*)d_in[0];
    const float* x   = (const float*)d_in[1];
    const float* ofx = (const float*)d_in[2];
    const int* src   = (const int*)d_in[3];
    const int* tgt   = (const int*)d_in[4];
    const float* RW[5] = {(const float*)d_in[5], (const float*)d_in[7], (const float*)d_in[9],
                          (const float*)d_in[11], (const float*)d_in[13]};
    const float* Rb[5] = {(const float*)d_in[6], (const float*)d_in[8], (const float*)d_in[10],
                          (const float*)d_in[12], (const float*)d_in[14]};
    const float* OW0 = (const float*)d_in[15];
    const float* Ob0 = (const float*)d_in[16];
    const float* OW1 = (const float*)d_in[17];
    const float* Ob1 = (const float*)d_in[18];
    float* out = (float*)d_out;

    const int M = in_sizes[3];
    const int N = in_sizes[1] / 4;

    __nv_bfloat16 *rpH, *rpL, *Xh, *Xl, *Yh, *Yl, *wst;
    float* ep;
    cudaGetSymbolAddress((void**)&rpH, g_rpH);
    cudaGetSymbolAddress((void**)&rpL, g_rpL);
    cudaGetSymbolAddress((void**)&Xh,  g_Xh);
    cudaGetSymbolAddress((void**)&Xl,  g_Xl);
    cudaGetSymbolAddress((void**)&Yh,  g_Yh);
    cudaGetSymbolAddress((void**)&Yl,  g_Yl);
    cudaGetSymbolAddress((void**)&ep,  g_eprime);
    cudaGetSymbolAddress((void**)&wst, g_wstage);

    int nsm = 148;
    cudaDeviceGetAttribute(&nsm, cudaDevAttrMultiProcessorCount, 0);

    // ---- weight prep: images [KD][WSTR] hi then lo ---------------------------
    // L0: 16x168 ; L1-3: 160x168 ; L4: 160x72
    const size_t woff[5] = {0, 5376, 5376 + 53760, 5376 + 2*53760, 5376 + 3*53760};
    const int wdin[5]  = {13, 150, 150, 150, 150};
    const int wdout[5] = {150, 150, 150, 150, 50};
    const int wKD[5]   = {16, 160, 160, 160, 160};
    const int wWSTR[5] = {168, 168, 168, 168, 72};
    const int wbrow[5] = {13, 150, 150, 150, 150};
    for (int i = 0; i < 5; i++) {
        int tot = wKD[i] * wWSTR[i];
        prep_w<<<(tot + 255) / 256, 256>>>(RW[i], Rb[i], wdin[i], wdout[i],
                                           wKD[i], wWSTR[i], wbrow[i], wst + woff[i]);
    }

    zero_kernel<<<(N * 64 + 255) / 256, 256>>>(ep, N * 64);
    gather_kernel<<<(M + 255) / 256, 256>>>(x, ofx, src, tgt, t, rpH, rpL, M);

    const size_t sm0 = fl_smem(1, 160, 10);
    const size_t sm1 = fl_smem(10, 160, 10);
    const size_t sm4 = fl_smem(10, 64, 8);
    cudaFuncSetAttribute(fused_layer<1, 160, 10, 1, 0>,  cudaFuncAttributeMaxDynamicSharedMemorySize, (int)sm0);
    cudaFuncSetAttribute(fused_layer<10, 160, 10, 1, 0>, cudaFuncAttributeMaxDynamicSharedMemorySize, (int)sm1);
    cudaFuncSetAttribute(fused_layer<10, 64, 4, 2, 1>,   cudaFuncAttributeMaxDynamicSharedMemorySize, (int)sm4);

    // ---- edge MLP -------------------------------------------------------------
    fused_layer<1, 160, 10, 1, 0> <<<nsm, 320, sm0>>>(rpH, rpL, wst + woff[0], Xh, Xl, nullptr, M, 150);
    fused_layer<10, 160, 10, 1, 0><<<nsm, 320, sm1>>>(Xh, Xl, wst + woff[1], Yh, Yl, nullptr, M, 150);
    fused_layer<10, 160, 10, 1, 0><<<nsm, 320, sm1>>>(Yh, Yl, wst + woff[2], Xh, Xl, nullptr, M, 150);
    fused_layer<10, 160, 10, 1, 0><<<nsm, 320, sm1>>>(Xh, Xl, wst + woff[3], Yh, Yl, nullptr, M, 150);
    float* E = (float*)Xh;   // X free after L3 consumed it
    fused_layer<10, 64, 4, 2, 1>  <<<nsm, 256, sm4>>>(Yh, Yl, wst + woff[4], nullptr, nullptr, E, M, -1);

    // ---- segment sum ------------------------------------------------------------
    scatter_kernel<<<(M * 32 + 255) / 256, 256>>>(E, tgt, ep, M);

    // ---- node MLP ----------------------------------------------------------------
    cudaFuncSetAttribute(gemm_kernel<4>, cudaFuncAttributeMaxDynamicSharedMemorySize, 112 * 1024);
    cudaFuncSetAttribute(gemm_kernel<1>, cudaFuncAttributeMaxDynamicSharedMemorySize, 112 * 1024);
    float* nb = (float*)rpH;   // reuse
    gemm_kernel<4><<<2 * nsm, 256, smbytes(50, 128)>>>(ep, 64, OW0, Ob0, nb, 128, N, 50, 100, 1, 1);
    gemm_kernel<1><<<2 * nsm, 256, smbytes(100, 32)>>>(nb, 128, OW1, Ob1, out, 4, N, 100, 4, 0, 0);
}